// round 14
// baseline (speedup 1.0000x reference)
#include <cuda_runtime.h>
#include <cuda_fp16.h>

#define BATCH   256
#define FEAT    4096
#define FMASK   (FEAT - 1)
#define CAP     256          // padded bin capacity per row (lambda=146.5, P(overflow)~1e-14)
#define TR_BLOCKS 1024       // transpose CTAs inside the merged prep kernel

// ---- scratch (device globals; no allocation allowed) ----
__device__ __half g_xTh[FEAT * BATCH];      // x transposed, fp16: (FEAT, BATCH), 2 MB
__device__ int    g_cnt[FEAT + 1];          // per-row nnz count + [FEAT] = row ticket
__device__ int2   g_bin[FEAT * CAP];        // packed {col, val(fp32)} bins, 8 MB

// ---- 1. merged prep: transpose+fp16-convert x  ||  scatter nnz into bins ----
__global__ void __launch_bounds__(256) prep(const float* __restrict__ x,
                                            const int* __restrict__ st,
                                            const float* __restrict__ stv,
                                            const int* __restrict__ sn,
                                            const float* __restrict__ snv,
                                            int nnzT, int nnzN) {
    if (blockIdx.x < TR_BLOCKS) {
        // ---- transpose path: 32x32 tile ----
        __shared__ float tile[32][33];
        int f0 = (blockIdx.x & 127) * 32;
        int b0 = (blockIdx.x >> 7) * 32;
        int i = threadIdx.x;
        {
            int row = i >> 3;            // batch row 0..31
            int q   = i & 7;             // feature quad 0..7
            float4 v = *(const float4*)&x[(b0 + row) * FEAT + f0 + q * 4];
            tile[row][q * 4 + 0] = v.x;
            tile[row][q * 4 + 1] = v.y;
            tile[row][q * 4 + 2] = v.z;
            tile[row][q * 4 + 3] = v.w;
        }
        __syncthreads();
        {
            int f  = i >> 3;             // feature 0..31
            int bq = i & 7;              // batch quad 0..7
            __half2 lo = __floats2half2_rn(tile[bq * 4 + 0][f], tile[bq * 4 + 1][f]);
            __half2 hi = __floats2half2_rn(tile[bq * 4 + 2][f], tile[bq * 4 + 3][f]);
            uint2 pack;
            pack.x = *(unsigned*)&lo;
            pack.y = *(unsigned*)&hi;
            *(uint2*)&g_xTh[(f0 + f) * BATCH + b0 + bq * 4] = pack;
        }
    } else {
        // ---- scatter path: one nnz per thread (proven fastest variant) ----
        int i = (blockIdx.x - TR_BLOCKS) * 256 + threadIdx.x;
        if (i >= nnzT + nnzN) return;
        int r, c; float v;
        if (i < nnzT) {
            r = st[i];
            c = st[nnzT + i];
            v = stv[i];
        } else {
            int j = i - nnzT;
            r = sn[j];
            c = sn[nnzN + j];
            v = snv[j];
        }
        r &= FMASK;
        int pos = atomicAdd(&g_cnt[r], 1) & (CAP - 1);   // mask = paranoia only
        g_bin[r * CAP + pos] = make_int2(c & FMASK, __float_as_int(v));
    }
}

// packed f32x2 fma: acc += xf2 * vv   (sm_103a FFMA2)
__device__ __forceinline__ void fma2p(unsigned long long& acc, float2 xf, unsigned long long vv) {
    unsigned long long xp;
    asm("mov.b64 %0, {%1, %2};" : "=l"(xp) : "f"(xf.x), "f"(xf.y));
    asm("fma.rn.f32x2 %0, %1, %2, %0;" : "+l"(acc) : "l"(xp), "l"(vv));
}

// ---- 2. main SpMM: warp-per-row, DYNAMIC row tickets at full concurrency.
//         2048 CTAs x 2 warps = 4096 warps (27.7/SM). Next ticket prefetched
//         at row start so its latency hides under the row's gather loop.
//         LDG.128 fp16 x loads, int4 bin loads, f32x2 FMA, direct output. ----
__global__ void __launch_bounds__(64) spmm_main(const float* __restrict__ bias,
                                                float* __restrict__ out) {
    int lane = threadIdx.x & 31;
    const uint4* xh = (const uint4*)g_xTh;              // row stride = 32 uint4

    int r = 0;
    if (lane == 0) r = atomicAdd(&g_cnt[FEAT], 1);
    r = __shfl_sync(0xffffffff, r, 0);

    while (r < FEAT) {
        // prefetch next ticket NOW; consumed at the end of this row
        int rn = 0;
        if (lane == 0) rn = atomicAdd(&g_cnt[FEAT], 1);

        int n = g_cnt[r];
        if (n > CAP) n = CAP;
        const int4* bp = (const int4*)(g_bin + r * CAP);   // 2 nnz per int4

        unsigned long long a0 = 0, a1 = 0, a2 = 0, a3 = 0;  // 8 fp32 accum as 4x f32x2

#define ACCQ(q, vbits)                                                   \
        {                                                                \
            float v = __int_as_float(vbits);                             \
            unsigned long long vv;                                       \
            asm("mov.b64 %0, {%1, %2};" : "=l"(vv) : "f"(v), "f"(v));    \
            fma2p(a0, __half22float2(*(__half2*)&q.x), vv);              \
            fma2p(a1, __half22float2(*(__half2*)&q.y), vv);              \
            fma2p(a2, __half22float2(*(__half2*)&q.z), vv);              \
            fma2p(a3, __half22float2(*(__half2*)&q.w), vv);              \
        }

        int j = 0;
        for (; j + 8 <= n; j += 8) {
            int4 b0 = __ldg(&bp[(j >> 1) + 0]);
            int4 b1 = __ldg(&bp[(j >> 1) + 1]);
            int4 b2 = __ldg(&bp[(j >> 1) + 2]);
            int4 b3 = __ldg(&bp[(j >> 1) + 3]);
            uint4 x0 = __ldg(&xh[b0.x * 32 + lane]);
            uint4 x1 = __ldg(&xh[b0.z * 32 + lane]);
            uint4 x2 = __ldg(&xh[b1.x * 32 + lane]);
            uint4 x3 = __ldg(&xh[b1.z * 32 + lane]);
            uint4 x4 = __ldg(&xh[b2.x * 32 + lane]);
            uint4 x5 = __ldg(&xh[b2.z * 32 + lane]);
            uint4 x6 = __ldg(&xh[b3.x * 32 + lane]);
            uint4 x7 = __ldg(&xh[b3.z * 32 + lane]);
            ACCQ(x0, b0.y) ACCQ(x1, b0.w)
            ACCQ(x2, b1.y) ACCQ(x3, b1.w)
            ACCQ(x4, b2.y) ACCQ(x5, b2.w)
            ACCQ(x6, b3.y) ACCQ(x7, b3.w)
        }
        for (; j < n; j++) {
            int2 p = __ldg(&g_bin[r * CAP + j]);
            uint4 xq = __ldg(&xh[p.x * 32 + lane]);
            ACCQ(xq, p.y)
        }
#undef ACCQ

        // unpack accumulators -> 8 floats
        float o0, o1, o2, o3, o4, o5, o6, o7;
        asm("mov.b64 {%0, %1}, %2;" : "=f"(o0), "=f"(o1) : "l"(a0));
        asm("mov.b64 {%0, %1}, %2;" : "=f"(o2), "=f"(o3) : "l"(a1));
        asm("mov.b64 {%0, %1}, %2;" : "=f"(o4), "=f"(o5) : "l"(a2));
        asm("mov.b64 {%0, %1}, %2;" : "=f"(o6), "=f"(o7) : "l"(a3));

        float bv = bias[r];
        int b = lane * 8;   // lane owns batches 8*lane .. 8*lane+7
        out[(b + 0) * FEAT + r] = o0 + bv;
        out[(b + 1) * FEAT + r] = o1 + bv;
        out[(b + 2) * FEAT + r] = o2 + bv;
        out[(b + 3) * FEAT + r] = o3 + bv;
        out[(b + 4) * FEAT + r] = o4 + bv;
        out[(b + 5) * FEAT + r] = o5 + bv;
        out[(b + 6) * FEAT + r] = o6 + bv;
        out[(b + 7) * FEAT + r] = o7 + bv;

        r = __shfl_sync(0xffffffff, rn, 0);
    }
}

extern "C" void kernel_launch(void* const* d_in, const int* in_sizes, int n_in,
                              void* d_out, int out_size) {
    const float* x       = (const float*)d_in[0];
    const int*   st_idx  = (const int*)d_in[1];
    const float* st_vals = (const float*)d_in[2];
    const int*   sn_idx  = (const int*)d_in[3];
    const float* sn_vals = (const float*)d_in[4];
    const float* bias    = (const float*)d_in[5];

    int nnzT  = in_sizes[2];
    int nnzN  = in_sizes[4];
    int total = nnzT + nnzN;

    // zero per-row counters + ticket with one memset node (graph-capturable)
    void* cnt_ptr = nullptr;
    cudaGetSymbolAddress(&cnt_ptr, g_cnt);
    cudaMemsetAsync(cnt_ptr, 0, (FEAT + 1) * sizeof(int));

    int scatter_blocks = (total + 255) / 256;
    prep<<<TR_BLOCKS + scatter_blocks, 256>>>(x, st_idx, st_vals, sn_idx, sn_vals, nnzT, nnzN);
    // 2048 CTAs x 2 warps = 4096 warps, dynamically consuming 4096 row tickets
    spmm_main<<<2048, 64>>>(bias, (float*)d_out);
}

// round 15
// speedup vs baseline: 1.4816x; 1.4816x over previous
#include <cuda_runtime.h>
#include <cuda_fp16.h>

#define BATCH   256
#define FEAT    4096
#define FMASK   (FEAT - 1)
#define SUBCAP  80           // capacity per sub-bin (Poisson(36.6), 7-sigma margin)
#define ROWCAP  (4 * SUBCAP) // 320 slots per row
#define TR_BLOCKS 1024       // transpose CTAs inside the merged prep kernel

// ---- scratch (device globals; no allocation allowed) ----
__device__ __half g_xTh[FEAT * BATCH];      // x transposed, fp16: (FEAT, BATCH), 2 MB
__device__ int    g_cnt[FEAT * 4];          // 4 sub-counters per row (memset node)
__device__ int2   g_bin[FEAT * ROWCAP];     // packed {col, val(fp32)} sub-bins, 10.5 MB

// ---- 1. merged prep: transpose+fp16-convert x  ||  scatter nnz into sub-bins ----
__global__ void __launch_bounds__(256) prep(const float* __restrict__ x,
                                            const int* __restrict__ st,
                                            const float* __restrict__ stv,
                                            const int* __restrict__ sn,
                                            const float* __restrict__ snv,
                                            int nnzT, int nnzN) {
    if (blockIdx.x < TR_BLOCKS) {
        // ---- transpose path: 32x32 tile ----
        __shared__ float tile[32][33];
        int f0 = (blockIdx.x & 127) * 32;
        int b0 = (blockIdx.x >> 7) * 32;
        int i = threadIdx.x;
        {
            int row = i >> 3;            // batch row 0..31
            int q   = i & 7;             // feature quad 0..7
            float4 v = *(const float4*)&x[(b0 + row) * FEAT + f0 + q * 4];
            tile[row][q * 4 + 0] = v.x;
            tile[row][q * 4 + 1] = v.y;
            tile[row][q * 4 + 2] = v.z;
            tile[row][q * 4 + 3] = v.w;
        }
        __syncthreads();
        {
            int f  = i >> 3;             // feature 0..31
            int bq = i & 7;              // batch quad 0..7
            __half2 lo = __floats2half2_rn(tile[bq * 4 + 0][f], tile[bq * 4 + 1][f]);
            __half2 hi = __floats2half2_rn(tile[bq * 4 + 2][f], tile[bq * 4 + 3][f]);
            uint2 pack;
            pack.x = *(unsigned*)&lo;
            pack.y = *(unsigned*)&hi;
            *(uint2*)&g_xTh[(f0 + f) * BATCH + b0 + bq * 4] = pack;
        }
    } else {
        // ---- scatter path: one nnz per thread, 4-way split row counters ----
        int i = (blockIdx.x - TR_BLOCKS) * 256 + threadIdx.x;
        if (i >= nnzT + nnzN) return;
        int r, c; float v;
        if (i < nnzT) {
            r = st[i];
            c = st[nnzT + i];
            v = stv[i];
        } else {
            int j = i - nnzT;
            r = sn[j];
            c = sn[nnzN + j];
            v = snv[j];
        }
        r &= FMASK;
        int sub = i & 3;                 // contention per counter: 146 -> ~37
        int pos = atomicAdd(&g_cnt[r * 4 + sub], 1);
        if (pos < SUBCAP)                // overflow P ~ 5e-9: guarded, never expected
            g_bin[r * ROWCAP + sub * SUBCAP + pos] = make_int2(c & FMASK, __float_as_int(v));
    }
}

// packed f32x2 fma: acc += xf2 * vv   (sm_103a FFMA2)
__device__ __forceinline__ void fma2p(unsigned long long& acc, float2 xf, unsigned long long vv) {
    unsigned long long xp;
    asm("mov.b64 %0, {%1, %2};" : "=l"(xp) : "f"(xf.x), "f"(xf.y));
    asm("fma.rn.f32x2 %0, %1, %2, %0;" : "+l"(acc) : "l"(xp), "l"(vv));
}

// ---- 2. main SpMM: r7's static warp-per-row schedule (proven best), iterating
//         the row's 4 sub-bins. LDG.128 fp16 x loads, int4 bin loads, f32x2 FMA. ----
__global__ void __launch_bounds__(64) spmm_main(const float* __restrict__ bias,
                                                float* __restrict__ out) {
    int warp = threadIdx.x >> 5;
    int lane = threadIdx.x & 31;
    int r = blockIdx.x * 2 + warp;

    int4 cn = *(const int4*)&g_cnt[r * 4];
    const uint4* xh = (const uint4*)g_xTh;              // row stride = 32 uint4

    unsigned long long a0 = 0, a1 = 0, a2 = 0, a3 = 0;  // 8 fp32 accum as 4x f32x2

#define ACCQ(q, vbits)                                                   \
    {                                                                    \
        float v = __int_as_float(vbits);                                 \
        unsigned long long vv;                                           \
        asm("mov.b64 %0, {%1, %2};" : "=l"(vv) : "f"(v), "f"(v));        \
        fma2p(a0, __half22float2(*(__half2*)&q.x), vv);                  \
        fma2p(a1, __half22float2(*(__half2*)&q.y), vv);                  \
        fma2p(a2, __half22float2(*(__half2*)&q.z), vv);                  \
        fma2p(a3, __half22float2(*(__half2*)&q.w), vv);                  \
    }

#pragma unroll
    for (int sub = 0; sub < 4; sub++) {
        int n = (sub == 0) ? cn.x : (sub == 1) ? cn.y : (sub == 2) ? cn.z : cn.w;
        if (n > SUBCAP) n = SUBCAP;
        const int2* bin = g_bin + r * ROWCAP + sub * SUBCAP;
        const int4* bp  = (const int4*)bin;             // sub-bin base is 16B-aligned

        int j = 0;
        for (; j + 8 <= n; j += 8) {
            int4 b0 = __ldg(&bp[(j >> 1) + 0]);
            int4 b1 = __ldg(&bp[(j >> 1) + 1]);
            int4 b2 = __ldg(&bp[(j >> 1) + 2]);
            int4 b3 = __ldg(&bp[(j >> 1) + 3]);
            uint4 x0 = __ldg(&xh[b0.x * 32 + lane]);
            uint4 x1 = __ldg(&xh[b0.z * 32 + lane]);
            uint4 x2 = __ldg(&xh[b1.x * 32 + lane]);
            uint4 x3 = __ldg(&xh[b1.z * 32 + lane]);
            uint4 x4 = __ldg(&xh[b2.x * 32 + lane]);
            uint4 x5 = __ldg(&xh[b2.z * 32 + lane]);
            uint4 x6 = __ldg(&xh[b3.x * 32 + lane]);
            uint4 x7 = __ldg(&xh[b3.z * 32 + lane]);
            ACCQ(x0, b0.y) ACCQ(x1, b0.w)
            ACCQ(x2, b1.y) ACCQ(x3, b1.w)
            ACCQ(x4, b2.y) ACCQ(x5, b2.w)
            ACCQ(x6, b3.y) ACCQ(x7, b3.w)
        }
        for (; j < n; j++) {
            int2 p = __ldg(&bin[j]);
            uint4 xq = __ldg(&xh[p.x * 32 + lane]);
            ACCQ(xq, p.y)
        }
    }
#undef ACCQ

    // unpack accumulators -> 8 floats
    float o0, o1, o2, o3, o4, o5, o6, o7;
    asm("mov.b64 {%0, %1}, %2;" : "=f"(o0), "=f"(o1) : "l"(a0));
    asm("mov.b64 {%0, %1}, %2;" : "=f"(o2), "=f"(o3) : "l"(a1));
    asm("mov.b64 {%0, %1}, %2;" : "=f"(o4), "=f"(o5) : "l"(a2));
    asm("mov.b64 {%0, %1}, %2;" : "=f"(o6), "=f"(o7) : "l"(a3));

    float bv = bias[r];
    int b = lane * 8;   // lane owns batches 8*lane .. 8*lane+7
    out[(b + 0) * FEAT + r] = o0 + bv;
    out[(b + 1) * FEAT + r] = o1 + bv;
    out[(b + 2) * FEAT + r] = o2 + bv;
    out[(b + 3) * FEAT + r] = o3 + bv;
    out[(b + 4) * FEAT + r] = o4 + bv;
    out[(b + 5) * FEAT + r] = o5 + bv;
    out[(b + 6) * FEAT + r] = o6 + bv;
    out[(b + 7) * FEAT + r] = o7 + bv;
}

extern "C" void kernel_launch(void* const* d_in, const int* in_sizes, int n_in,
                              void* d_out, int out_size) {
    const float* x       = (const float*)d_in[0];
    const int*   st_idx  = (const int*)d_in[1];
    const float* st_vals = (const float*)d_in[2];
    const int*   sn_idx  = (const int*)d_in[3];
    const float* sn_vals = (const float*)d_in[4];
    const float* bias    = (const float*)d_in[5];

    int nnzT  = in_sizes[2];
    int nnzN  = in_sizes[4];
    int total = nnzT + nnzN;

    // zero sub-counters with one memset node (graph-capturable, not an alloc)
    void* cnt_ptr = nullptr;
    cudaGetSymbolAddress(&cnt_ptr, g_cnt);
    cudaMemsetAsync(cnt_ptr, 0, FEAT * 4 * sizeof(int));

    int scatter_blocks = (total + 255) / 256;
    prep<<<TR_BLOCKS + scatter_blocks, 256>>>(x, st_idx, st_vals, sn_idx, sn_vals, nnzT, nnzN);
    // r7's proven static schedule: 2048 CTAs x 2 warps, warp-per-row
    spmm_main<<<FEAT / 2, 64>>>(bias, (float*)d_out);
}

// round 16
// speedup vs baseline: 1.5972x; 1.0780x over previous
#include <cuda_runtime.h>
#include <cuda_fp16.h>

#define BATCH   256
#define FEAT    4096
#define FMASK   (FEAT - 1)
#define SUBCAP  80           // capacity per sub-bin (Poisson(36.6), 7-sigma margin)
#define ROWCAP  (4 * SUBCAP) // 320 slots per row
#define TR_BLOCKS 1024       // transpose CTAs inside the merged prep kernel

// ---- scratch (device globals; no allocation allowed) ----
__device__ __half g_xTh[FEAT * BATCH];      // x transposed, fp16: (FEAT, BATCH), 2 MB
__device__ int    g_cnt[FEAT * 4];          // 4 sub-counters per row (memset node)
__device__ int2   g_bin[FEAT * ROWCAP];     // packed {col, val(fp32)} sub-bins, 10.5 MB

// ---- 1. merged prep: transpose+fp16-convert x  ||  scatter nnz into sub-bins ----
__global__ void __launch_bounds__(256) prep(const float* __restrict__ x,
                                            const int* __restrict__ st,
                                            const float* __restrict__ stv,
                                            const int* __restrict__ sn,
                                            const float* __restrict__ snv,
                                            int nnzT, int nnzN) {
    if (blockIdx.x < TR_BLOCKS) {
        // ---- transpose path: 32x32 tile ----
        __shared__ float tile[32][33];
        int f0 = (blockIdx.x & 127) * 32;
        int b0 = (blockIdx.x >> 7) * 32;
        int i = threadIdx.x;
        {
            int row = i >> 3;            // batch row 0..31
            int q   = i & 7;             // feature quad 0..7
            float4 v = *(const float4*)&x[(b0 + row) * FEAT + f0 + q * 4];
            tile[row][q * 4 + 0] = v.x;
            tile[row][q * 4 + 1] = v.y;
            tile[row][q * 4 + 2] = v.z;
            tile[row][q * 4 + 3] = v.w;
        }
        __syncthreads();
        {
            int f  = i >> 3;             // feature 0..31
            int bq = i & 7;              // batch quad 0..7
            __half2 lo = __floats2half2_rn(tile[bq * 4 + 0][f], tile[bq * 4 + 1][f]);
            __half2 hi = __floats2half2_rn(tile[bq * 4 + 2][f], tile[bq * 4 + 3][f]);
            uint2 pack;
            pack.x = *(unsigned*)&lo;
            pack.y = *(unsigned*)&hi;
            *(uint2*)&g_xTh[(f0 + f) * BATCH + b0 + bq * 4] = pack;
        }
    } else {
        // ---- scatter path: one nnz per thread, 4-way split row counters ----
        int i = (blockIdx.x - TR_BLOCKS) * 256 + threadIdx.x;
        if (i >= nnzT + nnzN) return;
        int r, c; float v;
        if (i < nnzT) {
            r = st[i];
            c = st[nnzT + i];
            v = stv[i];
        } else {
            int j = i - nnzT;
            r = sn[j];
            c = sn[nnzN + j];
            v = snv[j];
        }
        r &= FMASK;
        int sub = i & 3;                 // contention per counter: 146 -> ~37
        int pos = atomicAdd(&g_cnt[r * 4 + sub], 1);
        if (pos < SUBCAP)                // overflow P ~ 5e-9: guarded, never expected
            g_bin[r * ROWCAP + sub * SUBCAP + pos] = make_int2(c & FMASK, __float_as_int(v));
    }
}

// packed f32x2 fma: acc += xf2 * vv   (sm_103a FFMA2)
__device__ __forceinline__ void fma2p(unsigned long long& acc, float2 xf, unsigned long long vv) {
    unsigned long long xp;
    asm("mov.b64 %0, {%1, %2};" : "=l"(xp) : "f"(xf.x), "f"(xf.y));
    asm("fma.rn.f32x2 %0, %1, %2, %0;" : "+l"(acc) : "l"(xp), "l"(vv));
}

// ---- 2. main SpMM: CTA = one row, 4 warps = 4 equal sub-bins (~37 nnz each),
//         smem combine, direct output. 4096 CTAs -> ~2.4 waves: per-CTA
//         variation averages across waves instead of a global single-wave tail. ----
__global__ void __launch_bounds__(128) spmm_main(const float* __restrict__ bias,
                                                 float* __restrict__ out) {
    __shared__ float part[4][BATCH];     // 4 KB
    int sub  = threadIdx.x >> 5;         // warp = sub-bin 0..3
    int lane = threadIdx.x & 31;
    int r = blockIdx.x;

    int n = g_cnt[r * 4 + sub];
    if (n > SUBCAP) n = SUBCAP;
    const int2* bin = g_bin + r * ROWCAP + sub * SUBCAP;
    const int4* bp  = (const int4*)bin;                 // sub-bin base 16B-aligned
    const uint4* xh = (const uint4*)g_xTh;              // row stride = 32 uint4

    unsigned long long a0 = 0, a1 = 0, a2 = 0, a3 = 0;  // 8 fp32 accum as 4x f32x2

#define ACCQ(q, vbits)                                                   \
    {                                                                    \
        float v = __int_as_float(vbits);                                 \
        unsigned long long vv;                                           \
        asm("mov.b64 %0, {%1, %2};" : "=l"(vv) : "f"(v), "f"(v));        \
        fma2p(a0, __half22float2(*(__half2*)&q.x), vv);                  \
        fma2p(a1, __half22float2(*(__half2*)&q.y), vv);                  \
        fma2p(a2, __half22float2(*(__half2*)&q.z), vv);                  \
        fma2p(a3, __half22float2(*(__half2*)&q.w), vv);                  \
    }

    int j = 0;
    for (; j + 8 <= n; j += 8) {
        int4 b0 = __ldg(&bp[(j >> 1) + 0]);
        int4 b1 = __ldg(&bp[(j >> 1) + 1]);
        int4 b2 = __ldg(&bp[(j >> 1) + 2]);
        int4 b3 = __ldg(&bp[(j >> 1) + 3]);
        uint4 x0 = __ldg(&xh[b0.x * 32 + lane]);
        uint4 x1 = __ldg(&xh[b0.z * 32 + lane]);
        uint4 x2 = __ldg(&xh[b1.x * 32 + lane]);
        uint4 x3 = __ldg(&xh[b1.z * 32 + lane]);
        uint4 x4 = __ldg(&xh[b2.x * 32 + lane]);
        uint4 x5 = __ldg(&xh[b2.z * 32 + lane]);
        uint4 x6 = __ldg(&xh[b3.x * 32 + lane]);
        uint4 x7 = __ldg(&xh[b3.z * 32 + lane]);
        ACCQ(x0, b0.y) ACCQ(x1, b0.w)
        ACCQ(x2, b1.y) ACCQ(x3, b1.w)
        ACCQ(x4, b2.y) ACCQ(x5, b2.w)
        ACCQ(x6, b3.y) ACCQ(x7, b3.w)
    }
    for (; j < n; j++) {
        int2 p = __ldg(&bin[j]);
        uint4 xq = __ldg(&xh[p.x * 32 + lane]);
        ACCQ(xq, p.y)
    }
#undef ACCQ

    // unpack -> 8 floats, park in smem
    float o0, o1, o2, o3, o4, o5, o6, o7;
    asm("mov.b64 {%0, %1}, %2;" : "=f"(o0), "=f"(o1) : "l"(a0));
    asm("mov.b64 {%0, %1}, %2;" : "=f"(o2), "=f"(o3) : "l"(a1));
    asm("mov.b64 {%0, %1}, %2;" : "=f"(o4), "=f"(o5) : "l"(a2));
    asm("mov.b64 {%0, %1}, %2;" : "=f"(o6), "=f"(o7) : "l"(a3));
    int b = lane * 8;
    *(float4*)&part[sub][b]     = make_float4(o0, o1, o2, o3);
    *(float4*)&part[sub][b + 4] = make_float4(o4, o5, o6, o7);
    __syncthreads();

    // combine: thread t sums 2 batches over the 4 sub-partials, adds bias, stores
    float bv = __ldg(&bias[r]);
    int bb = threadIdx.x * 2;
#pragma unroll
    for (int k = 0; k < 2; k++) {
        int bi = bb + k;
        float s = part[0][bi] + part[1][bi] + part[2][bi] + part[3][bi];
        out[bi * FEAT + r] = s + bv;
    }
}

extern "C" void kernel_launch(void* const* d_in, const int* in_sizes, int n_in,
                              void* d_out, int out_size) {
    const float* x       = (const float*)d_in[0];
    const int*   st_idx  = (const int*)d_in[1];
    const float* st_vals = (const float*)d_in[2];
    const int*   sn_idx  = (const int*)d_in[3];
    const float* sn_vals = (const float*)d_in[4];
    const float* bias    = (const float*)d_in[5];

    int nnzT  = in_sizes[2];
    int nnzN  = in_sizes[4];
    int total = nnzT + nnzN;

    // zero sub-counters with one memset node (graph-capturable, not an alloc)
    void* cnt_ptr = nullptr;
    cudaGetSymbolAddress(&cnt_ptr, g_cnt);
    cudaMemsetAsync(cnt_ptr, 0, FEAT * 4 * sizeof(int));

    int scatter_blocks = (total + 255) / 256;
    prep<<<TR_BLOCKS + scatter_blocks, 256>>>(x, st_idx, st_vals, sn_idx, sn_vals, nnzT, nnzN);
    // CTA per row, 4 warps = 4 equal sub-bins, ~2.4 waves
    spmm_main<<<FEAT, 128>>>(bias, (float*)d_out);
}